// round 1
// baseline (speedup 1.0000x reference)
#include <cuda_runtime.h>
#include <cstring>

#define BB 8
#define QQ 500
#define CDIM 256
#define SPTS 8
#define QB 2
#define ROWS (SPTS*QB)
#define MEMROWS 8500
#define EMB_STRIDE 18   // 16 rows + 2 pad floats (keeps pair loads 8B-aligned, breaks store conflicts)
#define HPAD 4

// Packed f32x2 FMA (Blackwell-only; ptxas won't auto-fuse — must come from PTX)
__device__ __forceinline__ unsigned long long ffma2(unsigned long long a,
                                                    unsigned long long b,
                                                    unsigned long long c) {
    unsigned long long d;
    asm("fma.rn.f32x2 %0, %1, %2, %3;" : "=l"(d) : "l"(a), "l"(b), "l"(c));
    return d;
}
__device__ __forceinline__ unsigned long long pack2(float lo, float hi) {
    unsigned long long r;
    asm("mov.b64 %0, {%1, %2};" : "=l"(r) : "f"(lo), "f"(hi));
    return r;
}
__device__ __forceinline__ void unpack2(unsigned long long v, float& lo, float& hi) {
    asm("mov.b64 {%0, %1}, %2;" : "=f"(lo), "=f"(hi) : "l"(v));
}

__global__ void __launch_bounds__(256, 1)
decoder_fused_kernel(const float* __restrict__ ref_polys,
                     const int*   __restrict__ ref_levels,
                     const float* __restrict__ memory,
                     const float* __restrict__ W1,
                     const float* __restrict__ b1,
                     const float* __restrict__ W2,
                     const float* __restrict__ b2,
                     float*       __restrict__ out)
{
    __shared__ __align__(16) float s_emb[CDIM * EMB_STRIDE];   // [c][row] pair-interleaved
    __shared__ __align__(16) float s_h[ROWS][CDIM + HPAD];     // layer-1 activations
    __shared__ float s_spt[ROWS][2];
    __shared__ int   s_idx[ROWS][4];
    __shared__ float s_w[ROWS][4];

    const int bid   = blockIdx.x;
    const int b     = bid / (QQ / QB);
    const int qbase = (bid % (QQ / QB)) * QB;
    const int tid   = threadIdx.x;

    // ---- Phase 1: sampling points + bilinear corner setup (16 threads) ----
    if (tid < ROWS) {
        const int qi = tid >> 3;
        const int s  = tid & 7;
        const int q  = qbase + qi;
        const float* rp = ref_polys + (size_t)(b * QQ + q) * 8;
        const float lam = (float)s * (1.0f / 7.0f);
        // lambdas column d = lam^(3-d) -> Horner with coeffs [0..3]
        const float sx = 2.0f * ((((rp[0] * lam + rp[1]) * lam + rp[2]) * lam + rp[3]) - 0.5f);
        const float sy = 2.0f * ((((rp[4] * lam + rp[5]) * lam + rp[6]) * lam + rp[7]) - 0.5f);
        s_spt[tid][0] = sx;
        s_spt[tid][1] = sy;

        const int lvl = ref_levels[b * QQ + q];
        const int hs_tab[4] = {80, 40, 20, 10};
        const int st_tab[4] = {0, 6400, 8000, 8400};
        const int W  = hs_tab[lvl];          // square levels: H == W
        const int st = st_tab[lvl];

        const float gx = (sx + 1.0f) * 0.5f * (float)W - 0.5f;
        const float gy = (sy + 1.0f) * 0.5f * (float)W - 0.5f;
        const float x0f = floorf(gx), y0f = floorf(gy);
        const float fx = gx - x0f, fy = gy - y0f;
        const int x0 = (int)x0f, y0 = (int)y0f;
        const int base = b * MEMROWS + st;
        #pragma unroll
        for (int k = 0; k < 4; k++) {
            const int xi = x0 + (k & 1);
            const int yi = y0 + (k >> 1);
            const bool v = (xi >= 0) && (xi < W) && (yi >= 0) && (yi < W);
            s_idx[tid][k] = v ? (base + yi * W + xi) : -1;
            const float wx = (k & 1) ? fx : 1.0f - fx;
            const float wy = (k >> 1) ? fy : 1.0f - fy;
            s_w[tid][k] = wx * wy;
        }
    }
    __syncthreads();

    // ---- Phase 2: bilinear gather, emb -> smem (all 256 threads, one channel each) ----
    {
        const int c = tid;
        #pragma unroll
        for (int r = 0; r < ROWS; r++) {
            float e = 0.0f;
            #pragma unroll
            for (int k = 0; k < 4; k++) {
                const int idx = s_idx[r][k];
                if (idx >= 0)
                    e += s_w[r][k] * __ldg(memory + (size_t)idx * CDIM + c);
            }
            s_emb[c * EMB_STRIDE + r] = e;
        }
    }
    __syncthreads();

    // ---- Phase 3: layer 1 (emb @ W1 + b1 -> tanh), thread j = output column ----
    {
        const int j = tid;
        const float b1j = b1[j];
        unsigned long long acc[ROWS / 2];
        #pragma unroll
        for (int pr = 0; pr < ROWS / 2; pr++) acc[pr] = pack2(b1j, b1j);

        const float* w1p = W1 + j;
        #pragma unroll 4
        for (int c = 0; c < CDIM; c++) {
            const float wj = __ldg(w1p + c * CDIM);           // coalesced across threads
            const unsigned long long w2v = pack2(wj, wj);
            const unsigned long long* ep =
                (const unsigned long long*)(s_emb + c * EMB_STRIDE);  // broadcast LDS.64
            #pragma unroll
            for (int pr = 0; pr < ROWS / 2; pr++)
                acc[pr] = ffma2(ep[pr], w2v, acc[pr]);
        }
        #pragma unroll
        for (int pr = 0; pr < ROWS / 2; pr++) {
            float lo, hi;
            unpack2(acc[pr], lo, hi);
            s_h[2 * pr    ][j] = tanhf(lo);
            s_h[2 * pr + 1][j] = tanhf(hi);
        }
    }
    __syncthreads();

    // ---- Phase 4: layer 2 (h @ W2 + b2), tanh epilogue, write out (64 threads) ----
    if (tid < ROWS * 4) {
        const int r = tid >> 2;       // row 0..15
        const int p = tid & 3;        // output channel 0..3 (np*2 + coord)
        float sum = b2[p];
        const float* hp = s_h[r];
        #pragma unroll 8
        for (int jj = 0; jj < CDIM; jj++)
            sum += hp[jj] * __ldg(W2 + jj * 4 + p);
        const float off = 0.077f * tanhf(sum);
        const int qi = r >> 3, s = r & 7;
        const int q = qbase + qi;
        out[(size_t)(b * QQ + q) * 32 + s * 4 + p] = off + s_spt[r][p & 1];
    }
}

extern "C" void kernel_launch(void* const* d_in, const int* in_sizes, int n_in,
                              void* d_out, int out_size)
{
    const float* ref_polys  = (const float*)d_in[0];
    const int*   ref_levels = (const int*)  d_in[1];
    const float* memory     = (const float*)d_in[2];
    const float* W1         = (const float*)d_in[3];
    const float* b1         = (const float*)d_in[4];
    const float* W2         = (const float*)d_in[5];
    const float* b2         = (const float*)d_in[6];
    float* out = (float*)d_out;

    const int blocks = BB * QQ / QB;   // 2000
    decoder_fused_kernel<<<blocks, 256>>>(ref_polys, ref_levels, memory,
                                          W1, b1, W2, b2, out);
}

// round 3
// speedup vs baseline: 1.0084x; 1.0084x over previous
#include <cuda_runtime.h>
#include <cstring>

#define BB 8
#define QQ 500
#define CDIM 256
#define SPTS 8
#define QB 4
#define ROWS (SPTS*QB)          // 32
#define MEMROWS 8500
#define EMB_STRIDE 36           // 32 rows + 4 pad (keeps c*stride 16B-aligned for LDS.128)
#define HPAD 4

// Packed f32x2 FMA (Blackwell-only; must come from PTX)
__device__ __forceinline__ unsigned long long ffma2(unsigned long long a,
                                                    unsigned long long b,
                                                    unsigned long long c) {
    unsigned long long d;
    asm("fma.rn.f32x2 %0, %1, %2, %3;" : "=l"(d) : "l"(a), "l"(b), "l"(c));
    return d;
}
__device__ __forceinline__ unsigned long long pack2(float lo, float hi) {
    unsigned long long r;
    asm("mov.b64 %0, {%1, %2};" : "=l"(r) : "f"(lo), "f"(hi));
    return r;
}
__device__ __forceinline__ void unpack2(unsigned long long v, float& lo, float& hi) {
    asm("mov.b64 {%0, %1}, %2;" : "=f"(lo), "=f"(hi) : "l"(v));
}

__global__ void __launch_bounds__(256, 3)
decoder_fused_kernel(const float* __restrict__ ref_polys,
                     const int*   __restrict__ ref_levels,
                     const float* __restrict__ memory,
                     const float* __restrict__ W1,
                     const float* __restrict__ b1,
                     const float* __restrict__ W2,
                     const float* __restrict__ b2,
                     float*       __restrict__ out)
{
    __shared__ __align__(16) float s_emb[CDIM * EMB_STRIDE];   // [c][row] pair-interleaved
    __shared__ __align__(16) float s_h[ROWS][CDIM + HPAD];     // layer-1 activations
    __shared__ float s_spt[ROWS][2];
    __shared__ int   s_idx[ROWS][4];
    __shared__ float s_w[ROWS][4];

    const int bid   = blockIdx.x;
    const int b     = bid / (QQ / QB);
    const int qbase = (bid % (QQ / QB)) * QB;
    const int tid   = threadIdx.x;

    // ---- Phase 1: sampling points + bilinear corner setup (32 threads) ----
    if (tid < ROWS) {
        const int qi = tid >> 3;
        const int s  = tid & 7;
        const int q  = qbase + qi;
        const float* rp = ref_polys + (size_t)(b * QQ + q) * 8;
        const float lam = (float)s * (1.0f / 7.0f);
        const float sx = 2.0f * ((((rp[0] * lam + rp[1]) * lam + rp[2]) * lam + rp[3]) - 0.5f);
        const float sy = 2.0f * ((((rp[4] * lam + rp[5]) * lam + rp[6]) * lam + rp[7]) - 0.5f);
        s_spt[tid][0] = sx;
        s_spt[tid][1] = sy;

        const int lvl = ref_levels[b * QQ + q];
        const int hs_tab[4] = {80, 40, 20, 10};
        const int st_tab[4] = {0, 6400, 8000, 8400};
        const int W  = hs_tab[lvl];          // square levels: H == W
        const int st = st_tab[lvl];

        const float gx = (sx + 1.0f) * 0.5f * (float)W - 0.5f;
        const float gy = (sy + 1.0f) * 0.5f * (float)W - 0.5f;
        const float x0f = floorf(gx), y0f = floorf(gy);
        const float fx = gx - x0f, fy = gy - y0f;
        const int x0 = (int)x0f, y0 = (int)y0f;
        const int base = b * MEMROWS + st;
        #pragma unroll
        for (int k = 0; k < 4; k++) {
            const int xi = x0 + (k & 1);
            const int yi = y0 + (k >> 1);
            const bool v = (xi >= 0) && (xi < W) && (yi >= 0) && (yi < W);
            s_idx[tid][k] = v ? (base + yi * W + xi) : -1;
            const float wx = (k & 1) ? fx : 1.0f - fx;
            const float wy = (k >> 1) ? fy : 1.0f - fy;
            s_w[tid][k] = wx * wy;
        }
    }
    __syncthreads();

    // ---- Phase 2: bilinear gather, emb -> smem (all 256 threads, one channel each) ----
    {
        const int c = tid;
        #pragma unroll 8
        for (int r = 0; r < ROWS; r++) {
            float e = 0.0f;
            #pragma unroll
            for (int k = 0; k < 4; k++) {
                const int idx = s_idx[r][k];
                if (idx >= 0)
                    e += s_w[r][k] * __ldg(memory + (size_t)idx * CDIM + c);
            }
            s_emb[c * EMB_STRIDE + r] = e;
        }
    }
    __syncthreads();

    // ---- Phase 3: layer 1 (emb @ W1 + b1 -> tanh), thread j = output column ----
    {
        const int j = tid;
        const float b1j = b1[j];
        unsigned long long acc[ROWS / 2];
        #pragma unroll
        for (int pr = 0; pr < ROWS / 2; pr++) acc[pr] = pack2(b1j, b1j);

        const float* w1p = W1 + j;
        #pragma unroll 2
        for (int c = 0; c < CDIM; c++) {
            const float wj = __ldg(w1p + c * CDIM);            // coalesced across threads
            const unsigned long long w2v = pack2(wj, wj);
            const ulonglong2* ep =
                (const ulonglong2*)(s_emb + c * EMB_STRIDE);   // broadcast LDS.128
            #pragma unroll
            for (int pq = 0; pq < ROWS / 4; pq++) {
                const ulonglong2 v = ep[pq];
                acc[2 * pq    ] = ffma2(v.x, w2v, acc[2 * pq    ]);
                acc[2 * pq + 1] = ffma2(v.y, w2v, acc[2 * pq + 1]);
            }
        }
        #pragma unroll
        for (int pr = 0; pr < ROWS / 2; pr++) {
            float lo, hi;
            unpack2(acc[pr], lo, hi);
            s_h[2 * pr    ][j] = tanhf(lo);
            s_h[2 * pr + 1][j] = tanhf(hi);
        }
    }
    __syncthreads();

    // ---- Phase 4: layer 2 (h @ W2 + b2), tanh epilogue, write out (128 threads) ----
    if (tid < ROWS * 4) {
        const int r = tid >> 2;       // row 0..31
        const int p = tid & 3;        // output channel 0..3 (np*2 + coord)
        float sum = b2[p];
        const float4* hp = (const float4*)s_h[r];
        #pragma unroll 4
        for (int jj = 0; jj < CDIM / 4; jj++) {
            const float4 hv = hp[jj];
            sum += hv.x * __ldg(W2 + (4 * jj + 0) * 4 + p);
            sum += hv.y * __ldg(W2 + (4 * jj + 1) * 4 + p);
            sum += hv.z * __ldg(W2 + (4 * jj + 2) * 4 + p);
            sum += hv.w * __ldg(W2 + (4 * jj + 3) * 4 + p);
        }
        const float off = 0.077f * tanhf(sum);
        const int qi = r >> 3, s = r & 7;
        const int q = qbase + qi;
        out[(size_t)(b * QQ + q) * 32 + s * 4 + p] = off + s_spt[r][p & 1];
    }
}

extern "C" void kernel_launch(void* const* d_in, const int* in_sizes, int n_in,
                              void* d_out, int out_size)
{
    const float* ref_polys  = (const float*)d_in[0];
    const int*   ref_levels = (const int*)  d_in[1];
    const float* memory     = (const float*)d_in[2];
    const float* W1         = (const float*)d_in[3];
    const float* b1         = (const float*)d_in[4];
    const float* W2         = (const float*)d_in[5];
    const float* b2         = (const float*)d_in[6];
    float* out = (float*)d_out;

    const int blocks = BB * QQ / QB;   // 1000
    decoder_fused_kernel<<<blocks, 256>>>(ref_polys, ref_levels, memory,
                                          W1, b1, W2, b2, out);
}

// round 4
// speedup vs baseline: 1.0654x; 1.0566x over previous
#include <cuda_runtime.h>
#include <cstring>

#define BB 8
#define QQ 500
#define CDIM 256
#define SPTS 8
#define QB 4
#define ROWS (SPTS*QB)          // 32
#define MEMROWS 8500

// Packed f32x2 FMA (Blackwell-only; must come from PTX)
__device__ __forceinline__ unsigned long long ffma2(unsigned long long a,
                                                    unsigned long long b,
                                                    unsigned long long c) {
    unsigned long long d;
    asm("fma.rn.f32x2 %0, %1, %2, %3;" : "=l"(d) : "l"(a), "l"(b), "l"(c));
    return d;
}
__device__ __forceinline__ unsigned long long pack2(float lo, float hi) {
    unsigned long long r;
    asm("mov.b64 %0, {%1, %2};" : "=l"(r) : "f"(lo), "f"(hi));
    return r;
}
__device__ __forceinline__ void unpack2(unsigned long long v, float& lo, float& hi) {
    asm("mov.b64 {%0, %1}, %2;" : "=f"(lo), "=f"(hi) : "l"(v));
}
__device__ __forceinline__ float tanh_fast(float x) {
    float y;
    asm("tanh.approx.f32 %0, %1;" : "=f"(y) : "f"(x));
    return y;
}

__global__ void __launch_bounds__(256, 4)
decoder_fused_kernel(const float* __restrict__ ref_polys,
                     const int*   __restrict__ ref_levels,
                     const float* __restrict__ memory,
                     const float* __restrict__ W1,
                     const float* __restrict__ b1,
                     const float* __restrict__ W2,
                     const float* __restrict__ b2,
                     float*       __restrict__ out)
{
    // s_buf is a union: phase 2/3 use it as emb[c=0..255][32 rows, swizzled] (32 KB),
    // phase 3-epilogue/4 reuse it as h[r=0..31][256 cols, swizzled] (32 KB).
    __shared__ __align__(128) float s_buf[CDIM * 32];
    __shared__ __align__(16)  float s_w2t[4][CDIM];   // W2 transposed [p][jj]
    __shared__ float s_spt[ROWS][2];
    __shared__ int   s_idx[ROWS][4];
    __shared__ float s_w[ROWS][4];

    const int bid   = blockIdx.x;
    const int b     = bid / (QQ / QB);
    const int qbase = (bid % (QQ / QB)) * QB;
    const int tid   = threadIdx.x;
    char* const sb  = (char*)s_buf;

    // ---- Phase 1a: sampling points + bilinear corner setup (32 threads) ----
    if (tid < ROWS) {
        const int qi = tid >> 3;
        const int s  = tid & 7;
        const int q  = qbase + qi;
        const float* rp = ref_polys + (size_t)(b * QQ + q) * 8;
        const float lam = (float)s * (1.0f / 7.0f);
        const float sx = 2.0f * ((((rp[0] * lam + rp[1]) * lam + rp[2]) * lam + rp[3]) - 0.5f);
        const float sy = 2.0f * ((((rp[4] * lam + rp[5]) * lam + rp[6]) * lam + rp[7]) - 0.5f);
        s_spt[tid][0] = sx;
        s_spt[tid][1] = sy;

        const int lvl = ref_levels[b * QQ + q];
        const int hs_tab[4] = {80, 40, 20, 10};
        const int st_tab[4] = {0, 6400, 8000, 8400};
        const int W  = hs_tab[lvl];
        const int st = st_tab[lvl];

        const float gx = (sx + 1.0f) * 0.5f * (float)W - 0.5f;
        const float gy = (sy + 1.0f) * 0.5f * (float)W - 0.5f;
        const float x0f = floorf(gx), y0f = floorf(gy);
        const float fx = gx - x0f, fy = gy - y0f;
        const int x0 = (int)x0f, y0 = (int)y0f;
        const int base = b * MEMROWS + st;
        #pragma unroll
        for (int k = 0; k < 4; k++) {
            const int xi = x0 + (k & 1);
            const int yi = y0 + (k >> 1);
            const bool v = (xi >= 0) && (xi < W) && (yi >= 0) && (yi < W);
            s_idx[tid][k] = v ? (base + yi * W + xi) : -1;
            const float wx = (k & 1) ? fx : 1.0f - fx;
            const float wy = (k >> 1) ? fy : 1.0f - fy;
            s_w[tid][k] = wx * wy;
        }
    }
    // ---- Phase 1b: W2 transpose into smem (all threads) ----
    #pragma unroll
    for (int idx = tid; idx < 4 * CDIM; idx += 256) {
        const int p  = idx >> 8;
        const int jj = idx & 255;
        s_w2t[p][jj] = W2[jj * 4 + p];
    }
    __syncthreads();

    // ---- Phase 2: bilinear gather -> swizzled emb in s_buf (thread = channel c) ----
    {
        const int c = tid;
        const int sw = (c & 7) << 4;
        #pragma unroll 2
        for (int r4 = 0; r4 < 8; r4++) {          // 4 rows per float4 store
            float4 buf;
            float* bf = (float*)&buf;
            #pragma unroll
            for (int rr = 0; rr < 4; rr++) {
                const int r = r4 * 4 + rr;
                float e = 0.0f;
                #pragma unroll
                for (int k = 0; k < 4; k++) {
                    const int idx = s_idx[r][k];
                    if (idx >= 0)
                        e += s_w[r][k] * __ldg(memory + (size_t)idx * CDIM + c);
                }
                bf[rr] = e;
            }
            *(float4*)(sb + c * 128 + ((r4 << 4) ^ sw)) = buf;
        }
    }
    __syncthreads();

    // ---- Phase 3: layer 1 GEMM, thread tile = 8 rows x 4 cols ----
    {
        const int lane = tid & 31;
        const int rb   = lane & 3;                         // row block (8 rows)
        const int cb   = (lane >> 2) + ((tid >> 5) << 3);  // col block (4 cols), 0..63
        const int j0   = cb << 2;

        const float4 bv = __ldg((const float4*)(b1 + j0));
        unsigned long long acc[4][4];                      // [rowpair][col]
        #pragma unroll
        for (int p = 0; p < 4; p++) {
            acc[p][0] = pack2(bv.x, bv.x);
            acc[p][1] = pack2(bv.y, bv.y);
            acc[p][2] = pack2(bv.z, bv.z);
            acc[p][3] = pack2(bv.w, bv.w);
        }

        const char* ebase = sb;
        const int   roff0 = rb << 5;                       // rb*32
        #pragma unroll 2
        for (int c = 0; c < CDIM; c++) {
            const float4 w = __ldg((const float4*)(W1 + c * CDIM + j0));
            const int sw = (c & 7) << 4;
            const ulonglong2 eA = *(const ulonglong2*)(ebase + c * 128 + ((roff0 +  0) ^ sw));
            const ulonglong2 eB = *(const ulonglong2*)(ebase + c * 128 + ((roff0 + 16) ^ sw));
            const unsigned long long wv0 = pack2(w.x, w.x);
            const unsigned long long wv1 = pack2(w.y, w.y);
            const unsigned long long wv2 = pack2(w.z, w.z);
            const unsigned long long wv3 = pack2(w.w, w.w);
            acc[0][0] = ffma2(eA.x, wv0, acc[0][0]);
            acc[0][1] = ffma2(eA.x, wv1, acc[0][1]);
            acc[0][2] = ffma2(eA.x, wv2, acc[0][2]);
            acc[0][3] = ffma2(eA.x, wv3, acc[0][3]);
            acc[1][0] = ffma2(eA.y, wv0, acc[1][0]);
            acc[1][1] = ffma2(eA.y, wv1, acc[1][1]);
            acc[1][2] = ffma2(eA.y, wv2, acc[1][2]);
            acc[1][3] = ffma2(eA.y, wv3, acc[1][3]);
            acc[2][0] = ffma2(eB.x, wv0, acc[2][0]);
            acc[2][1] = ffma2(eB.x, wv1, acc[2][1]);
            acc[2][2] = ffma2(eB.x, wv2, acc[2][2]);
            acc[2][3] = ffma2(eB.x, wv3, acc[2][3]);
            acc[3][0] = ffma2(eB.y, wv0, acc[3][0]);
            acc[3][1] = ffma2(eB.y, wv1, acc[3][1]);
            acc[3][2] = ffma2(eB.y, wv2, acc[3][2]);
            acc[3][3] = ffma2(eB.y, wv3, acc[3][3]);
        }

        __syncthreads();   // all emb reads done before s_buf is reused as h

        // tanh + store h rows (8 rows x 4 cols) into s_buf as h[r][j], swizzled
        #pragma unroll
        for (int p = 0; p < 4; p++) {
            float lo0, hi0, lo1, hi1, lo2, hi2, lo3, hi3;
            unpack2(acc[p][0], lo0, hi0);
            unpack2(acc[p][1], lo1, hi1);
            unpack2(acc[p][2], lo2, hi2);
            unpack2(acc[p][3], lo3, hi3);
            const int r0 = (rb << 3) + (p << 1);
            const int r1 = r0 + 1;
            float4 v0 = make_float4(tanh_fast(lo0), tanh_fast(lo1), tanh_fast(lo2), tanh_fast(lo3));
            float4 v1 = make_float4(tanh_fast(hi0), tanh_fast(hi1), tanh_fast(hi2), tanh_fast(hi3));
            *(float4*)(sb + r0 * 1024 + (((unsigned)(j0 << 2)) ^ ((r0 & 7) << 4))) = v0;
            *(float4*)(sb + r1 * 1024 + (((unsigned)(j0 << 2)) ^ ((r1 & 7) << 4))) = v1;
        }
    }
    __syncthreads();

    // ---- Phase 4: layer 2 + tanh epilogue (all 256 threads; half-sums + shfl) ----
    {
        const int r    = tid >> 3;         // 0..31
        const int p    = (tid >> 1) & 3;   // 0..3
        const int half = tid & 1;
        const int sw   = (r & 7) << 4;
        const char* hrow = sb + r * 1024;

        unsigned long long acc2 = 0;
        float sum = 0.0f;
        const int jbyte0 = half << 9;      // half*512
        #pragma unroll 8
        for (int g = 0; g < 32; g++) {     // 32 float4 groups = 128 cols
            const int off = jbyte0 + (g << 4);
            const float4 hv = *(const float4*)(hrow + (off ^ sw));
            const float4 wv = *(const float4*)((const char*)s_w2t[p] + off);
            acc2 = ffma2(pack2(hv.x, hv.y), pack2(wv.x, wv.y), acc2);
            acc2 = ffma2(pack2(hv.z, hv.w), pack2(wv.z, wv.w), acc2);
        }
        {
            float lo, hi;
            unpack2(acc2, lo, hi);
            sum = lo + hi;
        }
        sum += __shfl_xor_sync(0xffffffffu, sum, 1);
        if (half == 0) {
            sum += __ldg(b2 + p);
            const float off = 0.077f * tanh_fast(sum);
            const int qi = r >> 3, s = r & 7;
            const int q = qbase + qi;
            out[(size_t)(b * QQ + q) * 32 + s * 4 + p] = off + s_spt[r][p & 1];
        }
    }
}

extern "C" void kernel_launch(void* const* d_in, const int* in_sizes, int n_in,
                              void* d_out, int out_size)
{
    const float* ref_polys  = (const float*)d_in[0];
    const int*   ref_levels = (const int*)  d_in[1];
    const float* memory     = (const float*)d_in[2];
    const float* W1         = (const float*)d_in[3];
    const float* b1         = (const float*)d_in[4];
    const float* W2         = (const float*)d_in[5];
    const float* b2         = (const float*)d_in[6];
    float* out = (float*)d_out;

    const int blocks = BB * QQ / QB;   // 1000
    decoder_fused_kernel<<<blocks, 256>>>(ref_polys, ref_levels, memory,
                                          W1, b1, W2, b2, out);
}